// round 6
// baseline (speedup 1.0000x reference)
#include <cuda_runtime.h>
#include <cuda_bf16.h>
#include <cstdint>

#define STEPS  30
#define HIDDEN 32
#define TPB    128
#define WARPS  (TPB / 32)        // 4
#define LPE    4                 // lanes per element
#define EPT    2                 // elements per thread-group
#define EPW    ((32 / LPE) * EPT)   // 16 elements per warp
#define EPC    (WARPS * EPW)        // 64 elements per CTA
#define HPAIRS (HIDDEN / LPE / 2)   // 4 hidden pairs per lane (8 units)

// ---------- packed f32x2 helpers (Blackwell sm_100+) ----------
__device__ __forceinline__ unsigned long long pack2(float lo, float hi) {
    unsigned long long r;
    asm("mov.b64 %0, {%1, %2};" : "=l"(r) : "f"(lo), "f"(hi));
    return r;
}
__device__ __forceinline__ void unpack2(unsigned long long v, float& lo, float& hi) {
    asm("mov.b64 {%0, %1}, %2;" : "=f"(lo), "=f"(hi) : "l"(v));
}
__device__ __forceinline__ unsigned long long fma2(unsigned long long a,
                                                   unsigned long long b,
                                                   unsigned long long c) {
    unsigned long long d;
    asm("fma.rn.f32x2 %0, %1, %2, %3;" : "=l"(d) : "l"(a), "l"(b), "l"(c));
    return d;
}
__device__ __forceinline__ unsigned long long add2(unsigned long long a,
                                                   unsigned long long b) {
    unsigned long long d;
    asm("add.rn.f32x2 %0, %1, %2;" : "=l"(d) : "l"(a), "l"(b));
    return d;
}
__device__ __forceinline__ unsigned long long relu2(unsigned long long v) {
    float lo, hi;
    unpack2(v, lo, hi);
    lo = fmaxf(lo, 0.0f);
    hi = fmaxf(hi, 0.0f);
    return pack2(lo, hi);
}

__global__ void __launch_bounds__(TPB, 6)
rhm_kernel(const float* __restrict__ S,
           const float* __restrict__ W1,
           const float* __restrict__ b1,
           const float* __restrict__ W2,
           const float* __restrict__ b2,
           const float* __restrict__ a_init,
           float* __restrict__ out,
           int B)
{
    // Staging: S rows on entry, d outputs on exit. Stride 31 -> conflict-free.
    __shared__ float sbuf[EPC][STEPS + 1];

    const int tid  = threadIdx.x;
    const int lane = tid & 31;
    const int wid  = tid >> 5;
    const int q    = lane & (LPE - 1);          // which 8 hidden units this lane owns
    const int e0   = wid * EPW + (lane >> 2);   // element A row (0..7 within warp)
    const int e1   = e0 + 8;                    // element B row

    const long long base = (long long)blockIdx.x * EPC;
    const int nvalid = (int)min((long long)EPC, (long long)B - base);
    const int ntot   = nvalid * STEPS;

    // ---- coalesced stage-in of S (64 rows x 30 floats = 1920 = 15*128) ----
    {
        const float* Sblk = S + base * STEPS;
        #pragma unroll
        for (int k = 0; k < (EPC * STEPS) / TPB; ++k) {
            int i = k * TPB + tid;
            if (i < ntot) {
                int el = i / STEPS;
                int st = i - el * STEPS;
                sbuf[el][st] = Sblk[i];
            }
        }
    }

    // ---- this lane's quarter of the weights: pairs [q*4, q*4+4) ----
    unsigned long long w0p[HPAIRS], w1p[HPAIRS], w2p[HPAIRS], b1p[HPAIRS], wop[HPAIRS];
    {
        const float2* W1f2 = reinterpret_cast<const float2*>(W1);  // (3,32) row-major
        const float2* b1f2 = reinterpret_cast<const float2*>(b1);
        const float2* W2f2 = reinterpret_cast<const float2*>(W2);  // (32,1)
        const int pbase = q * HPAIRS;
        #pragma unroll
        for (int j = 0; j < HPAIRS; ++j) {
            int p = pbase + j;
            float2 a = W1f2[p];       w0p[j] = pack2(a.x, a.y);
            float2 bb = W1f2[16 + p]; w1p[j] = pack2(bb.x, bb.y);
            float2 c = W1f2[32 + p];  w2p[j] = pack2(c.x, c.y);
            float2 dd = b1f2[p];      b1p[j] = pack2(dd.x, dd.y);
            float2 ee = W2f2[p];      wop[j] = pack2(ee.x, ee.y);
        }
    }
    const float bias2 = b2[0];
    const float dinit = a_init[0];

    float hA = 0.0f, hB = 0.0f;
    float dA = dinit, dB = dinit;

    __syncthreads();

    #pragma unroll 1
    for (int t = 0; t < STEPS; ++t) {
        float sA = sbuf[e0][t];
        float sB = sbuf[e1][t];

        unsigned long long s2A = pack2(sA, sA), s2B = pack2(sB, sB);
        unsigned long long d2A = pack2(dA, dA), d2B = pack2(dB, dB);
        unsigned long long h2A = pack2(hA, hA), h2B = pack2(hB, hB);

        unsigned long long accA0 = 0ull, accA1 = 0ull;
        unsigned long long accB0 = 0ull, accB1 = 0ull;

        #pragma unroll
        for (int j = 0; j < HPAIRS; ++j) {
            unsigned long long pA = fma2(s2A, w0p[j], b1p[j]);
            unsigned long long pB = fma2(s2B, w0p[j], b1p[j]);
            pA = fma2(d2A, w1p[j], pA);
            pB = fma2(d2B, w1p[j], pB);
            pA = fma2(h2A, w2p[j], pA);
            pB = fma2(h2B, w2p[j], pB);
            pA = relu2(pA);
            pB = relu2(pB);
            if (j & 1) { accA1 = fma2(pA, wop[j], accA1); accB1 = fma2(pB, wop[j], accB1); }
            else       { accA0 = fma2(pA, wop[j], accA0); accB0 = fma2(pB, wop[j], accB0); }
        }

        float loA, hiA, loB, hiB;
        unpack2(add2(accA0, accA1), loA, hiA);
        unpack2(add2(accB0, accB1), loB, hiB);
        float mA = loA + hiA;                    // this lane's 8-unit partial
        float mB = loB + hiB;

        // 2-level butterfly across the 4 lanes of each element
        mA += __shfl_xor_sync(0xffffffffu, mA, 1);
        mB += __shfl_xor_sync(0xffffffffu, mB, 1);
        mA += __shfl_xor_sync(0xffffffffu, mA, 2);
        mB += __shfl_xor_sync(0xffffffffu, mB, 2);

        float dnA = mA + bias2;
        float dnB = mB + bias2;

        hA = 0.8f * hA + 0.2f * dnA;
        hB = 0.8f * hB + 0.2f * dnB;
        dA = dnA;
        dB = dnB;
        if (q == 0) {
            sbuf[e0][t] = dnA;
            sbuf[e1][t] = dnB;
        }
    }

    __syncthreads();

    // ---- coalesced flush ----
    {
        float* Oblk = out + base * STEPS;
        #pragma unroll
        for (int k = 0; k < (EPC * STEPS) / TPB; ++k) {
            int i = k * TPB + tid;
            if (i < ntot) {
                int el = i / STEPS;
                int st = i - el * STEPS;
                Oblk[i] = sbuf[el][st];
            }
        }
    }
}

extern "C" void kernel_launch(void* const* d_in, const int* in_sizes, int n_in,
                              void* d_out, int out_size)
{
    const float* S      = (const float*)d_in[0];
    const float* W1     = (const float*)d_in[1];
    const float* b1     = (const float*)d_in[2];
    const float* W2     = (const float*)d_in[3];
    const float* b2     = (const float*)d_in[4];
    const float* a_init = (const float*)d_in[5];
    float* out = (float*)d_out;

    int B = in_sizes[0] / STEPS;
    int grid = (B + EPC - 1) / EPC;
    rhm_kernel<<<grid, TPB>>>(S, W1, b1, W2, b2, a_init, out, B);
}

// round 8
// speedup vs baseline: 1.0184x; 1.0184x over previous
#include <cuda_runtime.h>
#include <cuda_bf16.h>
#include <cstdint>

#define STEPS  30
#define HIDDEN 32
#define TPB    128
#define WARPS  (TPB / 32)        // 4
#define EPT    3                 // elements per lane-pair
#define EPW    (16 * EPT)        // 48 elements per warp
#define EPC    (WARPS * EPW)     // 192 elements per CTA
#define HPAIRS 8                 // hidden pairs per lane (16 units, half-split)

// ---------- packed f32x2 helpers (Blackwell sm_100+) ----------
__device__ __forceinline__ unsigned long long pack2(float lo, float hi) {
    unsigned long long r;
    asm("mov.b64 %0, {%1, %2};" : "=l"(r) : "f"(lo), "f"(hi));
    return r;
}
__device__ __forceinline__ void unpack2(unsigned long long v, float& lo, float& hi) {
    asm("mov.b64 {%0, %1}, %2;" : "=f"(lo), "=f"(hi) : "l"(v));
}
__device__ __forceinline__ unsigned long long fma2(unsigned long long a,
                                                   unsigned long long b,
                                                   unsigned long long c) {
    unsigned long long d;
    asm("fma.rn.f32x2 %0, %1, %2, %3;" : "=l"(d) : "l"(a), "l"(b), "l"(c));
    return d;
}
__device__ __forceinline__ unsigned long long add2(unsigned long long a,
                                                   unsigned long long b) {
    unsigned long long d;
    asm("add.rn.f32x2 %0, %1, %2;" : "=l"(d) : "l"(a), "l"(b));
    return d;
}
// ReLU on the scalar halves: 2 FMNMX on the (underused) alu pipe.
__device__ __forceinline__ unsigned long long relu2(unsigned long long v) {
    float lo, hi;
    unpack2(v, lo, hi);
    lo = fmaxf(lo, 0.0f);
    hi = fmaxf(hi, 0.0f);
    return pack2(lo, hi);
}

__global__ void __launch_bounds__(TPB, 3)
rhm_kernel(const float* __restrict__ S,
           const float* __restrict__ W1,
           const float* __restrict__ b1,
           const float* __restrict__ W2,
           const float* __restrict__ b2,
           const float* __restrict__ a_init,
           float* __restrict__ out,
           int B)
{
    // Staging: S rows on entry, d outputs on exit. Stride 31 -> conflict-free.
    __shared__ float sbuf[EPC][STEPS + 1];

    const int tid  = threadIdx.x;
    const int lane = tid & 31;
    const int wid  = tid >> 5;
    const int half = lane & 1;                  // which 16 hidden units this lane owns
    const int e0   = wid * EPW + (lane >> 1);   // element A row
    const int e1   = e0 + 16;                   // element B row
    const int e2   = e0 + 32;                   // element C row

    const long long base = (long long)blockIdx.x * EPC;
    const int nvalid = (int)min((long long)EPC, (long long)B - base);
    const int ntot   = nvalid * STEPS;

    // ---- coalesced stage-in of S (192 rows x 30 floats) ----
    {
        const float* Sblk = S + base * STEPS;
        #pragma unroll
        for (int k = 0; k < (EPC * STEPS) / TPB; ++k) {
            int i = k * TPB + tid;
            if (i < ntot) {
                int el = i / STEPS;
                int st = i - el * STEPS;
                sbuf[el][st] = Sblk[i];
            }
        }
    }

    // ---- this lane's half of the weights: units [half*16, half*16+16) ----
    unsigned long long w0p[HPAIRS], w1p[HPAIRS], w2p[HPAIRS], b1p[HPAIRS], wop[HPAIRS];
    {
        const float2* W1f2 = reinterpret_cast<const float2*>(W1);  // (3,32) row-major
        const float2* b1f2 = reinterpret_cast<const float2*>(b1);
        const float2* W2f2 = reinterpret_cast<const float2*>(W2);  // (32,1)
        const int pbase = half * HPAIRS;
        #pragma unroll
        for (int j = 0; j < HPAIRS; ++j) {
            int p = pbase + j;
            float2 a = W1f2[p];       w0p[j] = pack2(a.x, a.y);
            float2 bb = W1f2[16 + p]; w1p[j] = pack2(bb.x, bb.y);
            float2 c = W1f2[32 + p];  w2p[j] = pack2(c.x, c.y);
            float2 dd = b1f2[p];      b1p[j] = pack2(dd.x, dd.y);
            float2 ee = W2f2[p];      wop[j] = pack2(ee.x, ee.y);
        }
    }
    const float bias2 = b2[0];
    const float dinit = a_init[0];

    float hA = 0.0f, hB = 0.0f, hC = 0.0f;
    float dA = dinit, dB = dinit, dC = dinit;

    __syncthreads();

    // Prefetch step-0 inputs; keep a one-step-ahead pipeline so the 29-cyc LDS
    // never sits on the step-serial chain. Column STEPS (=30) is in-bounds
    // padding (sbuf has STEPS+1 columns), read but never used.
    float sA = sbuf[e0][0];
    float sB = sbuf[e1][0];
    float sC = sbuf[e2][0];

    #pragma unroll 1
    for (int t = 0; t < STEPS; ++t) {
        float nA = sbuf[e0][t + 1];
        float nB = sbuf[e1][t + 1];
        float nC = sbuf[e2][t + 1];

        unsigned long long s2A = pack2(sA, sA), s2B = pack2(sB, sB), s2C = pack2(sC, sC);
        unsigned long long d2A = pack2(dA, dA), d2B = pack2(dB, dB), d2C = pack2(dC, dC);
        unsigned long long h2A = pack2(hA, hA), h2B = pack2(hB, hB), h2C = pack2(hC, hC);

        unsigned long long accA0 = 0ull, accA1 = 0ull;
        unsigned long long accB0 = 0ull, accB1 = 0ull;
        unsigned long long accC0 = 0ull, accC1 = 0ull;

        #pragma unroll
        for (int j = 0; j < HPAIRS; ++j) {
            unsigned long long pA = fma2(s2A, w0p[j], b1p[j]);
            unsigned long long pB = fma2(s2B, w0p[j], b1p[j]);
            unsigned long long pC = fma2(s2C, w0p[j], b1p[j]);
            pA = fma2(d2A, w1p[j], pA);
            pB = fma2(d2B, w1p[j], pB);
            pC = fma2(d2C, w1p[j], pC);
            pA = fma2(h2A, w2p[j], pA);
            pB = fma2(h2B, w2p[j], pB);
            pC = fma2(h2C, w2p[j], pC);
            pA = relu2(pA);
            pB = relu2(pB);
            pC = relu2(pC);
            if (j & 1) {
                accA1 = fma2(pA, wop[j], accA1);
                accB1 = fma2(pB, wop[j], accB1);
                accC1 = fma2(pC, wop[j], accC1);
            } else {
                accA0 = fma2(pA, wop[j], accA0);
                accB0 = fma2(pB, wop[j], accB0);
                accC0 = fma2(pC, wop[j], accC0);
            }
        }

        float loA, hiA, loB, hiB, loC, hiC;
        unpack2(add2(accA0, accA1), loA, hiA);
        unpack2(add2(accB0, accB1), loB, hiB);
        unpack2(add2(accC0, accC1), loC, hiC);
        float mA = loA + hiA;
        float mB = loB + hiB;
        float mC = loC + hiC;
        mA += __shfl_xor_sync(0xffffffffu, mA, 1);
        mB += __shfl_xor_sync(0xffffffffu, mB, 1);
        mC += __shfl_xor_sync(0xffffffffu, mC, 1);

        float dnA = mA + bias2;
        float dnB = mB + bias2;
        float dnC = mC + bias2;

        hA = 0.8f * hA + 0.2f * dnA;
        hB = 0.8f * hB + 0.2f * dnB;
        hC = 0.8f * hC + 0.2f * dnC;
        dA = dnA; dB = dnB; dC = dnC;
        if (half == 0) {
            sbuf[e0][t] = dnA;
            sbuf[e1][t] = dnB;
            sbuf[e2][t] = dnC;
        }
        sA = nA; sB = nB; sC = nC;
    }

    __syncthreads();

    // ---- coalesced flush ----
    {
        float* Oblk = out + base * STEPS;
        #pragma unroll
        for (int k = 0; k < (EPC * STEPS) / TPB; ++k) {
            int i = k * TPB + tid;
            if (i < ntot) {
                int el = i / STEPS;
                int st = i - el * STEPS;
                Oblk[i] = sbuf[el][st];
            }
        }
    }
}

extern "C" void kernel_launch(void* const* d_in, const int* in_sizes, int n_in,
                              void* d_out, int out_size)
{
    const float* S      = (const float*)d_in[0];
    const float* W1     = (const float*)d_in[1];
    const float* b1     = (const float*)d_in[2];
    const float* W2     = (const float*)d_in[3];
    const float* b2     = (const float*)d_in[4];
    const float* a_init = (const float*)d_in[5];
    float* out = (float*)d_out;

    int B = in_sizes[0] / STEPS;
    int grid = (B + EPC - 1) / EPC;
    rhm_kernel<<<grid, TPB>>>(S, W1, b1, W2, b2, a_init, out, B);
}

// round 9
// speedup vs baseline: 1.0296x; 1.0110x over previous
#include <cuda_runtime.h>
#include <cuda_bf16.h>
#include <cstdint>

#define STEPS  30
#define HIDDEN 32
#define TPB    128
#define WARPS  (TPB / 32)        // 4
#define EPT    2                 // elements per lane-pair
#define EPW    (16 * EPT)        // 32 elements per warp
#define EPC    (WARPS * EPW)     // 128 elements per CTA
#define HPAIRS 8                 // hidden pairs per lane (16 units, half-split)

// ---------- packed f32x2 helpers (Blackwell sm_100+) ----------
__device__ __forceinline__ unsigned long long pack2(float lo, float hi) {
    unsigned long long r;
    asm("mov.b64 %0, {%1, %2};" : "=l"(r) : "f"(lo), "f"(hi));
    return r;
}
__device__ __forceinline__ void unpack2(unsigned long long v, float& lo, float& hi) {
    asm("mov.b64 {%0, %1}, %2;" : "=f"(lo), "=f"(hi) : "l"(v));
}
__device__ __forceinline__ unsigned long long fma2(unsigned long long a,
                                                   unsigned long long b,
                                                   unsigned long long c) {
    unsigned long long d;
    asm("fma.rn.f32x2 %0, %1, %2, %3;" : "=l"(d) : "l"(a), "l"(b), "l"(c));
    return d;
}
__device__ __forceinline__ unsigned long long add2(unsigned long long a,
                                                   unsigned long long b) {
    unsigned long long d;
    asm("add.rn.f32x2 %0, %1, %2;" : "=l"(d) : "l"(a), "l"(b));
    return d;
}
__device__ __forceinline__ unsigned long long relu2(unsigned long long v) {
    float lo, hi;
    unpack2(v, lo, hi);
    lo = fmaxf(lo, 0.0f);
    hi = fmaxf(hi, 0.0f);
    return pack2(lo, hi);
}

__global__ void __launch_bounds__(TPB, 4)
rhm_kernel(const float* __restrict__ S,
           const float* __restrict__ W1,
           const float* __restrict__ b1,
           const float* __restrict__ W2,
           const float* __restrict__ b2,
           const float* __restrict__ a_init,
           float* __restrict__ out,
           int B)
{
    // Staging: S rows on entry, d outputs on exit. Stride 31 -> conflict-free.
    __shared__ float sbuf[EPC][STEPS + 1];

    const int tid  = threadIdx.x;
    const int lane = tid & 31;
    const int wid  = tid >> 5;
    const int half = lane & 1;                  // which 16 hidden units this lane owns
    const int e0   = wid * EPW + (lane >> 1);   // element A row
    const int e1   = e0 + 16;                   // element B row

    const long long base = (long long)blockIdx.x * EPC;
    const int nvalid = (int)min((long long)EPC, (long long)B - base);
    const int ntot   = nvalid * STEPS;

    // ---- coalesced stage-in of S (128 rows x 30 floats) ----
    {
        const float* Sblk = S + base * STEPS;
        #pragma unroll
        for (int k = 0; k < (EPC * STEPS) / TPB; ++k) {
            int i = k * TPB + tid;
            if (i < ntot) {
                int el = i / STEPS;
                int st = i - el * STEPS;
                sbuf[el][st] = Sblk[i];
            }
        }
    }

    // ---- this lane's half of the weights: units [half*16, half*16+16) ----
    unsigned long long w0p[HPAIRS], w1p[HPAIRS], w2p[HPAIRS], b1p[HPAIRS], wop[HPAIRS];
    {
        const float2* W1f2 = reinterpret_cast<const float2*>(W1);  // (3,32) row-major
        const float2* b1f2 = reinterpret_cast<const float2*>(b1);
        const float2* W2f2 = reinterpret_cast<const float2*>(W2);  // (32,1)
        const int pbase = half * HPAIRS;
        #pragma unroll
        for (int j = 0; j < HPAIRS; ++j) {
            int p = pbase + j;
            float2 a = W1f2[p];       w0p[j] = pack2(a.x, a.y);
            float2 bb = W1f2[16 + p]; w1p[j] = pack2(bb.x, bb.y);
            float2 c = W1f2[32 + p];  w2p[j] = pack2(c.x, c.y);
            float2 dd = b1f2[p];      b1p[j] = pack2(dd.x, dd.y);
            float2 ee = W2f2[p];      wop[j] = pack2(ee.x, ee.y);
        }
    }
    const float bias2 = b2[0];
    const float dinit = a_init[0];

    float hA = 0.0f, hB = 0.0f;
    float dA = dinit, dB = dinit;

    __syncthreads();

    // ---- de-phase CTAs sharing an SMSP so step tails interleave instead of
    //      colliding on the fma port. Deterministic (pure function of bid). ----
    {
        unsigned slot = ((unsigned)blockIdx.x * 2654435761u) >> 30;  // 0..3
        if (slot) __nanosleep(slot * 120u);
    }

    // Prefetch step-0 s; one-step-ahead so the LDS stays off the serial tail.
    // Column STEPS (=30) is in-bounds padding, read but never used.
    float sA = sbuf[e0][0];
    float sB = sbuf[e1][0];

    #pragma unroll 1
    for (int t = 0; t < STEPS; ++t) {
        float nA = sbuf[e0][t + 1];
        float nB = sbuf[e1][t + 1];

        unsigned long long s2A = pack2(sA, sA), s2B = pack2(sB, sB);
        unsigned long long d2A = pack2(dA, dA), d2B = pack2(dB, dB);
        unsigned long long h2A = pack2(hA, hA), h2B = pack2(hB, hB);

        unsigned long long accA0 = 0ull, accA1 = 0ull;
        unsigned long long accB0 = 0ull, accB1 = 0ull;

        #pragma unroll
        for (int j = 0; j < HPAIRS; ++j) {
            unsigned long long pA = fma2(s2A, w0p[j], b1p[j]);
            unsigned long long pB = fma2(s2B, w0p[j], b1p[j]);
            pA = fma2(d2A, w1p[j], pA);
            pB = fma2(d2B, w1p[j], pB);
            pA = fma2(h2A, w2p[j], pA);
            pB = fma2(h2B, w2p[j], pB);
            pA = relu2(pA);
            pB = relu2(pB);
            if (j & 1) { accA1 = fma2(pA, wop[j], accA1); accB1 = fma2(pB, wop[j], accB1); }
            else       { accA0 = fma2(pA, wop[j], accA0); accB0 = fma2(pB, wop[j], accB0); }
        }

        float loA, hiA, loB, hiB;
        unpack2(add2(accA0, accA1), loA, hiA);
        unpack2(add2(accB0, accB1), loB, hiB);
        float mA = loA + hiA;
        float mB = loB + hiB;
        mA += __shfl_xor_sync(0xffffffffu, mA, 1);
        mB += __shfl_xor_sync(0xffffffffu, mB, 1);

        float dnA = mA + bias2;
        float dnB = mB + bias2;

        hA = 0.8f * hA + 0.2f * dnA;
        hB = 0.8f * hB + 0.2f * dnB;
        dA = dnA;
        dB = dnB;
        if (half == 0) {
            sbuf[e0][t] = dnA;
            sbuf[e1][t] = dnB;
        }
        sA = nA;
        sB = nB;
    }

    __syncthreads();

    // ---- coalesced flush ----
    {
        float* Oblk = out + base * STEPS;
        #pragma unroll
        for (int k = 0; k < (EPC * STEPS) / TPB; ++k) {
            int i = k * TPB + tid;
            if (i < ntot) {
                int el = i / STEPS;
                int st = i - el * STEPS;
                Oblk[i] = sbuf[el][st];
            }
        }
    }
}

extern "C" void kernel_launch(void* const* d_in, const int* in_sizes, int n_in,
                              void* d_out, int out_size)
{
    const float* S      = (const float*)d_in[0];
    const float* W1     = (const float*)d_in[1];
    const float* b1     = (const float*)d_in[2];
    const float* W2     = (const float*)d_in[3];
    const float* b2     = (const float*)d_in[4];
    const float* a_init = (const float*)d_in[5];
    float* out = (float*)d_out;

    int B = in_sizes[0] / STEPS;
    int grid = (B + EPC - 1) / EPC;
    rhm_kernel<<<grid, TPB>>>(S, W1, b1, W2, b2, a_init, out, B);
}

// round 10
// speedup vs baseline: 1.0470x; 1.0169x over previous
#include <cuda_runtime.h>
#include <cuda_bf16.h>
#include <cstdint>

#define STEPS  30
#define HIDDEN 32
#define TPB    128
#define WARPS  (TPB / 32)        // 4
#define EPT    2                 // elements per lane-pair
#define EPW    (16 * EPT)        // 32 elements per warp
#define EPC    (WARPS * EPW)     // 128 elements per CTA
#define HPAIRS 8                 // hidden pairs per lane (16 units, half-split)

// ---------- packed f32x2 helpers (Blackwell sm_100+) ----------
__device__ __forceinline__ unsigned long long pack2(float lo, float hi) {
    unsigned long long r;
    asm("mov.b64 %0, {%1, %2};" : "=l"(r) : "f"(lo), "f"(hi));
    return r;
}
__device__ __forceinline__ void unpack2(unsigned long long v, float& lo, float& hi) {
    asm("mov.b64 {%0, %1}, %2;" : "=f"(lo), "=f"(hi) : "l"(v));
}
__device__ __forceinline__ unsigned long long fma2(unsigned long long a,
                                                   unsigned long long b,
                                                   unsigned long long c) {
    unsigned long long d;
    asm("fma.rn.f32x2 %0, %1, %2, %3;" : "=l"(d) : "l"(a), "l"(b), "l"(c));
    return d;
}
__device__ __forceinline__ unsigned long long add2(unsigned long long a,
                                                   unsigned long long b) {
    unsigned long long d;
    asm("add.rn.f32x2 %0, %1, %2;" : "=l"(d) : "l"(a), "l"(b));
    return d;
}
__device__ __forceinline__ unsigned long long relu2(unsigned long long v) {
    float lo, hi;
    unpack2(v, lo, hi);
    lo = fmaxf(lo, 0.0f);
    hi = fmaxf(hi, 0.0f);
    return pack2(lo, hi);
}

// One element's step: multiplicand-phased passes so consecutive FFMA2s share
// srcA (operand-reuse cache cuts RF reads, the measured bottleneck).
__device__ __forceinline__ float elem_step(
    float s, float d, float h,
    const unsigned long long* __restrict__ w0p,
    const unsigned long long* __restrict__ w1p,
    const unsigned long long* __restrict__ w2p,
    const unsigned long long* __restrict__ b1p,
    const unsigned long long* __restrict__ wop)
{
    unsigned long long s2 = pack2(s, s);
    unsigned long long d2 = pack2(d, d);
    unsigned long long h2 = pack2(h, h);

    unsigned long long p[HPAIRS];

    // pass 1: x s2  (srcA constant across 8 consecutive FFMA2s -> .reuse)
    #pragma unroll
    for (int j = 0; j < HPAIRS; ++j) p[j] = fma2(s2, w0p[j], b1p[j]);
    // pass 2: x d2
    #pragma unroll
    for (int j = 0; j < HPAIRS; ++j) p[j] = fma2(d2, w1p[j], p[j]);
    // pass 3: x h2
    #pragma unroll
    for (int j = 0; j < HPAIRS; ++j) p[j] = fma2(h2, w2p[j], p[j]);
    // relu (alu pipe)
    #pragma unroll
    for (int j = 0; j < HPAIRS; ++j) p[j] = relu2(p[j]);
    // dot with W2
    unsigned long long a0 = 0ull, a1 = 0ull;
    #pragma unroll
    for (int j = 0; j < HPAIRS; j += 2) {
        a0 = fma2(p[j],     wop[j],     a0);
        a1 = fma2(p[j + 1], wop[j + 1], a1);
    }
    float lo, hi;
    unpack2(add2(a0, a1), lo, hi);
    return lo + hi;   // this lane's 16-unit partial
}

__global__ void __launch_bounds__(TPB, 4)
rhm_kernel(const float* __restrict__ S,
           const float* __restrict__ W1,
           const float* __restrict__ b1,
           const float* __restrict__ W2,
           const float* __restrict__ b2,
           const float* __restrict__ a_init,
           float* __restrict__ out,
           int B)
{
    __shared__ float sbuf[EPC][STEPS + 1];

    const int tid  = threadIdx.x;
    const int lane = tid & 31;
    const int wid  = tid >> 5;
    const int half = lane & 1;
    const int e0   = wid * EPW + (lane >> 1);
    const int e1   = e0 + 16;

    const long long base = (long long)blockIdx.x * EPC;
    const int nvalid = (int)min((long long)EPC, (long long)B - base);
    const int ntot   = nvalid * STEPS;

    // ---- coalesced stage-in of S ----
    {
        const float* Sblk = S + base * STEPS;
        #pragma unroll
        for (int k = 0; k < (EPC * STEPS) / TPB; ++k) {
            int i = k * TPB + tid;
            if (i < ntot) {
                int el = i / STEPS;
                int st = i - el * STEPS;
                sbuf[el][st] = Sblk[i];
            }
        }
    }

    // ---- this lane's half of the weights ----
    unsigned long long w0p[HPAIRS], w1p[HPAIRS], w2p[HPAIRS], b1p[HPAIRS], wop[HPAIRS];
    {
        const float2* W1f2 = reinterpret_cast<const float2*>(W1);  // (3,32)
        const float2* b1f2 = reinterpret_cast<const float2*>(b1);
        const float2* W2f2 = reinterpret_cast<const float2*>(W2);  // (32,1)
        const int pbase = half * HPAIRS;
        #pragma unroll
        for (int j = 0; j < HPAIRS; ++j) {
            int p = pbase + j;
            float2 a = W1f2[p];       w0p[j] = pack2(a.x, a.y);
            float2 bb = W1f2[16 + p]; w1p[j] = pack2(bb.x, bb.y);
            float2 c = W1f2[32 + p];  w2p[j] = pack2(c.x, c.y);
            float2 dd = b1f2[p];      b1p[j] = pack2(dd.x, dd.y);
            float2 ee = W2f2[p];      wop[j] = pack2(ee.x, ee.y);
        }
    }
    const float bias2 = b2[0];
    const float dinit = a_init[0];

    float hA = 0.0f, hB = 0.0f;
    float dA = dinit, dB = dinit;

    __syncthreads();

    // One-step-ahead s prefetch (column STEPS is in-bounds padding).
    float sA = sbuf[e0][0];
    float sB = sbuf[e1][0];

    #pragma unroll 1
    for (int t = 0; t < STEPS; ++t) {
        float nA = sbuf[e0][t + 1];
        float nB = sbuf[e1][t + 1];

        // Element A step (phased, reuse-friendly), then B; A's shuffle/tail
        // overlaps B's FMA passes via scoreboarding.
        float mA = elem_step(sA, dA, hA, w0p, w1p, w2p, b1p, wop);
        mA += __shfl_xor_sync(0xffffffffu, mA, 1);
        float mB = elem_step(sB, dB, hB, w0p, w1p, w2p, b1p, wop);
        mB += __shfl_xor_sync(0xffffffffu, mB, 1);

        float dnA = mA + bias2;
        float dnB = mB + bias2;

        hA = 0.8f * hA + 0.2f * dnA;
        hB = 0.8f * hB + 0.2f * dnB;
        dA = dnA;
        dB = dnB;
        if (half == 0) {
            sbuf[e0][t] = dnA;
            sbuf[e1][t] = dnB;
        }
        sA = nA;
        sB = nB;
    }

    __syncthreads();

    // ---- coalesced flush ----
    {
        float* Oblk = out + base * STEPS;
        #pragma unroll
        for (int k = 0; k < (EPC * STEPS) / TPB; ++k) {
            int i = k * TPB + tid;
            if (i < ntot) {
                int el = i / STEPS;
                int st = i - el * STEPS;
                Oblk[i] = sbuf[el][st];
            }
        }
    }
}

extern "C" void kernel_launch(void* const* d_in, const int* in_sizes, int n_in,
                              void* d_out, int out_size)
{
    const float* S      = (const float*)d_in[0];
    const float* W1     = (const float*)d_in[1];
    const float* b1     = (const float*)d_in[2];
    const float* W2     = (const float*)d_in[3];
    const float* b2     = (const float*)d_in[4];
    const float* a_init = (const float*)d_in[5];
    float* out = (float*)d_out;

    int B = in_sizes[0] / STEPS;
    int grid = (B + EPC - 1) / EPC;
    rhm_kernel<<<grid, TPB>>>(S, W1, b1, W2, b2, a_init, out, B);
}

// round 11
// speedup vs baseline: 1.0821x; 1.0334x over previous
#include <cuda_runtime.h>
#include <cuda_bf16.h>
#include <cstdint>

#define STEPS  30
#define HIDDEN 32
#define TPB    128
#define WARPS  (TPB / 32)          // 4
#define LPE    4                   // lanes cooperating per element-pair
#define PPW    8                   // element-pairs per warp (32/LPE)
#define EPC    (WARPS * PPW * 2)   // 64 elements per CTA
#define UNITS  (HIDDEN / LPE)      // 8 hidden units per lane

// ---------- packed f32x2 helpers (Blackwell sm_100+) ----------
__device__ __forceinline__ unsigned long long pack2(float lo, float hi) {
    unsigned long long r;
    asm("mov.b64 %0, {%1, %2};" : "=l"(r) : "f"(lo), "f"(hi));
    return r;
}
__device__ __forceinline__ void unpack2(unsigned long long v, float& lo, float& hi) {
    asm("mov.b64 {%0, %1}, %2;" : "=f"(lo), "=f"(hi) : "l"(v));
}
__device__ __forceinline__ unsigned long long fma2(unsigned long long a,
                                                   unsigned long long b,
                                                   unsigned long long c) {
    unsigned long long d;
    asm("fma.rn.f32x2 %0, %1, %2, %3;" : "=l"(d) : "l"(a), "l"(b), "l"(c));
    return d;
}
__device__ __forceinline__ unsigned long long add2(unsigned long long a,
                                                   unsigned long long b) {
    unsigned long long d;
    asm("add.rn.f32x2 %0, %1, %2;" : "=l"(d) : "l"(a), "l"(b));
    return d;
}
__device__ __forceinline__ unsigned long long mul2(unsigned long long a,
                                                   unsigned long long b) {
    unsigned long long d;
    asm("mul.rn.f32x2 %0, %1, %2;" : "=l"(d) : "l"(a), "l"(b));
    return d;
}
// ReLU on both packed halves, in place (FMNMX writes pair halves directly).
__device__ __forceinline__ unsigned long long relu2(unsigned long long v) {
    float lo, hi;
    unpack2(v, lo, hi);
    lo = fmaxf(lo, 0.0f);
    hi = fmaxf(hi, 0.0f);
    return pack2(lo, hi);
}

__global__ void __launch_bounds__(TPB, 4)
rhm_kernel(const float* __restrict__ S,
           const float* __restrict__ W1,
           const float* __restrict__ b1,
           const float* __restrict__ W2,
           const float* __restrict__ b2,
           const float* __restrict__ a_init,
           float* __restrict__ out,
           int B)
{
    // sbuf2[pair][step]: .x = element 2*pair, .y = element 2*pair+1.
    // 32 pairs x 31 steps x 8B. Row stride 62 floats -> conflict-free.
    __shared__ float2 sbuf2[EPC / 2][STEPS + 1];
    float* const sbufF = reinterpret_cast<float*>(sbuf2);

    const int tid  = threadIdx.x;
    const int lane = tid & 31;
    const int wid  = tid >> 5;
    const int q    = lane & (LPE - 1);             // this lane's unit-quarter
    const int pair = wid * PPW + (lane >> 2);      // pair row (0..31)

    const long long base = (long long)blockIdx.x * EPC;
    const int nvalid = (int)min((long long)EPC, (long long)B - base);
    const int ntot   = nvalid * STEPS;

    // ---- coalesced stage-in: S[elem][step] -> sbuf2[elem>>1][step].{x|y} ----
    {
        const float* Sblk = S + base * STEPS;
        #pragma unroll
        for (int k = 0; k < (EPC * STEPS) / TPB; ++k) {
            int i = k * TPB + tid;
            if (i < ntot) {
                int el = i / STEPS;
                int st = i - el * STEPS;
                sbufF[(el >> 1) * (2 * (STEPS + 1)) + st * 2 + (el & 1)] = Sblk[i];
            }
        }
    }

    // ---- broadcast weight pairs for this lane's 8 units ----
    unsigned long long w0b[UNITS], w1b[UNITS], w2b[UNITS], b1b[UNITS], wob[UNITS];
    {
        const int ubase = q * UNITS;
        #pragma unroll
        for (int j = 0; j < UNITS; ++j) {
            int u = ubase + j;
            float a = W1[u];            w0b[j] = pack2(a, a);     // W1[0][u]
            float bb = W1[HIDDEN + u];  w1b[j] = pack2(bb, bb);   // W1[1][u]
            float c = W1[2*HIDDEN + u]; w2b[j] = pack2(c, c);     // W1[2][u]
            float dd = b1[u];           b1b[j] = pack2(dd, dd);
            float ee = W2[u];           wob[j] = pack2(ee, ee);
        }
    }
    const float b2s = b2[0];
    const float din = a_init[0];
    const unsigned long long c08 = pack2(0.8f, 0.8f);
    const unsigned long long c02 = pack2(0.2f, 0.2f);
    const unsigned long long cb2 = pack2(b2s, b2s);

    unsigned long long h2 = 0ull;               // (0.f, 0.f)
    unsigned long long d2 = pack2(din, din);

    __syncthreads();

    // One-step-ahead s-pair prefetch (column STEPS is in-bounds padding).
    unsigned long long s2 =
        *reinterpret_cast<const unsigned long long*>(&sbuf2[pair][0]);

    #pragma unroll 1
    for (int t = 0; t < STEPS; ++t) {
        unsigned long long sn =
            *reinterpret_cast<const unsigned long long*>(&sbuf2[pair][t + 1]);

        unsigned long long acc0 = 0ull, acc1 = 0ull;

        #pragma unroll
        for (int j = 0; j < UNITS; ++j) {
            unsigned long long p = fma2(s2, w0b[j], b1b[j]);
            p = fma2(d2, w1b[j], p);
            p = fma2(h2, w2b[j], p);
            p = relu2(p);
            if (j & 1) acc1 = fma2(p, wob[j], acc1);
            else       acc0 = fma2(p, wob[j], acc0);
        }

        unsigned long long m2 = add2(acc0, acc1);     // this lane's 8-unit partials
        // 2-level 64-bit butterfly across the 4 lanes of the group
        m2 = add2(m2, __shfl_xor_sync(0xffffffffu, m2, 1));
        m2 = add2(m2, __shfl_xor_sync(0xffffffffu, m2, 2));

        unsigned long long dn2 = add2(m2, cb2);       // + b2 (both elements)

        h2 = fma2(h2, c08, mul2(dn2, c02));           // h = .8h + .2d
        d2 = dn2;
        if (q == 0)
            *reinterpret_cast<unsigned long long*>(&sbuf2[pair][t]) = dn2;
        s2 = sn;
    }

    __syncthreads();

    // ---- coalesced flush ----
    {
        float* Oblk = out + base * STEPS;
        #pragma unroll
        for (int k = 0; k < (EPC * STEPS) / TPB; ++k) {
            int i = k * TPB + tid;
            if (i < ntot) {
                int el = i / STEPS;
                int st = i - el * STEPS;
                Oblk[i] = sbufF[(el >> 1) * (2 * (STEPS + 1)) + st * 2 + (el & 1)];
            }
        }
    }
}

extern "C" void kernel_launch(void* const* d_in, const int* in_sizes, int n_in,
                              void* d_out, int out_size)
{
    const float* S      = (const float*)d_in[0];
    const float* W1     = (const float*)d_in[1];
    const float* b1     = (const float*)d_in[2];
    const float* W2     = (const float*)d_in[3];
    const float* b2     = (const float*)d_in[4];
    const float* a_init = (const float*)d_in[5];
    float* out = (float*)d_out;

    int B = in_sizes[0] / STEPS;
    int grid = (B + EPC - 1) / EPC;
    rhm_kernel<<<grid, TPB>>>(S, W1, b1, W2, b2, a_init, out, B);
}

// round 12
// speedup vs baseline: 1.0913x; 1.0086x over previous
#include <cuda_runtime.h>
#include <cuda_bf16.h>
#include <cstdint>

#define STEPS  30
#define HIDDEN 32
#define TPB    128
#define WARPS  (TPB / 32)          // 4
#define LPE    4                   // lanes cooperating per element-pair
#define PPT    2                   // element-pairs per lane group
#define PPW    (8 * PPT)           // element-pairs per warp = 16
#define EPC    (WARPS * PPW * 2)   // 128 elements per CTA
#define UNITS  (HIDDEN / LPE)      // 8 hidden units per lane

// ---------- packed f32x2 helpers (Blackwell sm_100+) ----------
__device__ __forceinline__ unsigned long long pack2(float lo, float hi) {
    unsigned long long r;
    asm("mov.b64 %0, {%1, %2};" : "=l"(r) : "f"(lo), "f"(hi));
    return r;
}
__device__ __forceinline__ void unpack2(unsigned long long v, float& lo, float& hi) {
    asm("mov.b64 {%0, %1}, %2;" : "=f"(lo), "=f"(hi) : "l"(v));
}
__device__ __forceinline__ unsigned long long fma2(unsigned long long a,
                                                   unsigned long long b,
                                                   unsigned long long c) {
    unsigned long long d;
    asm("fma.rn.f32x2 %0, %1, %2, %3;" : "=l"(d) : "l"(a), "l"(b), "l"(c));
    return d;
}
__device__ __forceinline__ unsigned long long add2(unsigned long long a,
                                                   unsigned long long b) {
    unsigned long long d;
    asm("add.rn.f32x2 %0, %1, %2;" : "=l"(d) : "l"(a), "l"(b));
    return d;
}
__device__ __forceinline__ unsigned long long mul2(unsigned long long a,
                                                   unsigned long long b) {
    unsigned long long d;
    asm("mul.rn.f32x2 %0, %1, %2;" : "=l"(d) : "l"(a), "l"(b));
    return d;
}
__device__ __forceinline__ unsigned long long relu2(unsigned long long v) {
    float lo, hi;
    unpack2(v, lo, hi);
    lo = fmaxf(lo, 0.0f);
    hi = fmaxf(hi, 0.0f);
    return pack2(lo, hi);
}

__global__ void __launch_bounds__(TPB, 4)
rhm_kernel(const float* __restrict__ S,
           const float* __restrict__ W1,
           const float* __restrict__ b1,
           const float* __restrict__ W2,
           const float* __restrict__ b2,
           const float* __restrict__ a_init,
           float* __restrict__ out,
           int B)
{
    // sbuf2[pair][step]: .x = element 2*pair, .y = element 2*pair+1.
    __shared__ float2 sbuf2[EPC / 2][STEPS + 1];
    float* const sbufF = reinterpret_cast<float*>(sbuf2);

    const int tid  = threadIdx.x;
    const int lane = tid & 31;
    const int wid  = tid >> 5;
    const int q    = lane & (LPE - 1);             // this lane's unit-quarter
    const int pr0  = wid * PPW + (lane >> 2);      // pair row A (0..63)
    const int pr1  = pr0 + 8;                      // pair row B

    const long long base = (long long)blockIdx.x * EPC;
    const int nvalid = (int)min((long long)EPC, (long long)B - base);
    const int ntot   = nvalid * STEPS;

    // ---- coalesced stage-in ----
    {
        const float* Sblk = S + base * STEPS;
        #pragma unroll
        for (int k = 0; k < (EPC * STEPS) / TPB; ++k) {
            int i = k * TPB + tid;
            if (i < ntot) {
                int el = i / STEPS;
                int st = i - el * STEPS;
                sbufF[(el >> 1) * (2 * (STEPS + 1)) + st * 2 + (el & 1)] = Sblk[i];
            }
        }
    }

    // ---- broadcast weight pairs for this lane's 8 units ----
    unsigned long long w0b[UNITS], w1b[UNITS], w2b[UNITS], b1b[UNITS], wob[UNITS];
    {
        const int ubase = q * UNITS;
        #pragma unroll
        for (int j = 0; j < UNITS; ++j) {
            int u = ubase + j;
            float a = W1[u];            w0b[j] = pack2(a, a);
            float bb = W1[HIDDEN + u];  w1b[j] = pack2(bb, bb);
            float c = W1[2*HIDDEN + u]; w2b[j] = pack2(c, c);
            float dd = b1[u];           b1b[j] = pack2(dd, dd);
            float ee = W2[u];           wob[j] = pack2(ee, ee);
        }
    }
    const float b2s = b2[0];
    const float din = a_init[0];
    const unsigned long long c08 = pack2(0.8f, 0.8f);
    const unsigned long long c02 = pack2(0.2f, 0.2f);
    const unsigned long long cb2 = pack2(b2s, b2s);

    unsigned long long h2a = 0ull, h2b = 0ull;
    unsigned long long d2a = pack2(din, din), d2b = d2a;

    __syncthreads();

    // One-step-ahead s-pair prefetch (column STEPS is in-bounds padding).
    unsigned long long s2a =
        *reinterpret_cast<const unsigned long long*>(&sbuf2[pr0][0]);
    unsigned long long s2b =
        *reinterpret_cast<const unsigned long long*>(&sbuf2[pr1][0]);

    #pragma unroll 1
    for (int t = 0; t < STEPS; ++t) {
        unsigned long long sna =
            *reinterpret_cast<const unsigned long long*>(&sbuf2[pr0][t + 1]);
        unsigned long long snb =
            *reinterpret_cast<const unsigned long long*>(&sbuf2[pr1][t + 1]);

        unsigned long long accA0 = 0ull, accA1 = 0ull;
        unsigned long long accB0 = 0ull, accB1 = 0ull;

        #pragma unroll
        for (int j = 0; j < UNITS; ++j) {
            unsigned long long pa = fma2(s2a, w0b[j], b1b[j]);
            unsigned long long pb = fma2(s2b, w0b[j], b1b[j]);
            pa = fma2(d2a, w1b[j], pa);
            pb = fma2(d2b, w1b[j], pb);
            pa = fma2(h2a, w2b[j], pa);
            pb = fma2(h2b, w2b[j], pb);
            pa = relu2(pa);
            pb = relu2(pb);
            if (j & 1) { accA1 = fma2(pa, wob[j], accA1); accB1 = fma2(pb, wob[j], accB1); }
            else       { accA0 = fma2(pa, wob[j], accA0); accB0 = fma2(pb, wob[j], accB0); }
        }

        unsigned long long mA = add2(accA0, accA1);
        unsigned long long mB = add2(accB0, accB1);
        mA = add2(mA, __shfl_xor_sync(0xffffffffu, mA, 1));
        mB = add2(mB, __shfl_xor_sync(0xffffffffu, mB, 1));
        mA = add2(mA, __shfl_xor_sync(0xffffffffu, mA, 2));
        mB = add2(mB, __shfl_xor_sync(0xffffffffu, mB, 2));

        unsigned long long dnA = add2(mA, cb2);
        unsigned long long dnB = add2(mB, cb2);

        h2a = fma2(h2a, c08, mul2(dnA, c02));
        h2b = fma2(h2b, c08, mul2(dnB, c02));
        d2a = dnA;
        d2b = dnB;
        if (q == 0) {
            *reinterpret_cast<unsigned long long*>(&sbuf2[pr0][t]) = dnA;
            *reinterpret_cast<unsigned long long*>(&sbuf2[pr1][t]) = dnB;
        }
        s2a = sna;
        s2b = snb;
    }

    __syncthreads();

    // ---- coalesced flush ----
    {
        float* Oblk = out + base * STEPS;
        #pragma unroll
        for (int k = 0; k < (EPC * STEPS) / TPB; ++k) {
            int i = k * TPB + tid;
            if (i < ntot) {
                int el = i / STEPS;
                int st = i - el * STEPS;
                Oblk[i] = sbufF[(el >> 1) * (2 * (STEPS + 1)) + st * 2 + (el & 1)];
            }
        }
    }
}

extern "C" void kernel_launch(void* const* d_in, const int* in_sizes, int n_in,
                              void* d_out, int out_size)
{
    const float* S      = (const float*)d_in[0];
    const float* W1     = (const float*)d_in[1];
    const float* b1     = (const float*)d_in[2];
    const float* W2     = (const float*)d_in[3];
    const float* b2     = (const float*)d_in[4];
    const float* a_init = (const float*)d_in[5];
    float* out = (float*)d_out;

    int B = in_sizes[0] / STEPS;
    int grid = (B + EPC - 1) / EPC;
    rhm_kernel<<<grid, TPB>>>(S, W1, b1, W2, b2, a_init, out, B);
}